// round 9
// baseline (speedup 1.0000x reference)
#include <cuda_runtime.h>
#include <cstdint>

// input f32 [4,64,512,512], gathered f32 [2048,64,16,16], indices (b,hb,wb)
// int32 or int64 (detected on device). stride==kernel==16 -> 4096 disjoint
// 16x16 slots; duplicates via per-slot linked lists. Main pass:
// out = in + sum(patches in slot), 640MB traffic, 256-bit streaming accesses,
// persistent grid-stride main kernel (152 SMs x 8 CTAs) with cross-iteration
// prefetch of the in-stream and slot heads.
//
// Epoch trick removes head-init: heads are u64 (epoch<<32|patch). g_ctr is
// bumped once per build block (8/launch); all blocks of one launch share
// epoch=(ctr>>3)+1 since launches are stream-serialized. Stale heads fail the
// epoch compare. Main kernel is PDL-launched; first in-load precedes
// griddepcontrol.wait.

#define BB 4
#define CC 64
#define HH 512
#define WW 512
#define NN 2048
#define NSLOTS 4096            // BB * 32 * 32
#define TOTAL8 8388608u        // BB*CC*HH*WW / 8
#define GRID_MAIN 1216         // 152 SMs * 8 CTAs
#define STRIDE8 (GRID_MAIN * 256u)

__device__ unsigned long long g_slot[NSLOTS];  // (epoch<<32) | patch_id
__device__ int g_next[NN];
__device__ unsigned g_ctr;                     // monotonic, +8 per launch
__device__ unsigned g_epoch;                   // current epoch (written by build)

// 8 blocks x 256 threads = exactly NN.
// Dtype detect per block: first 3072 u64 words = 24576B (full buffer if
// int32 = N*3*4, half if int64). Genuine int64 index values are < 512 so all
// high words are zero; int32 data read as u64 carries the neighboring field
// in the high word (nonzero somewhere with overwhelming probability).
__global__ void __launch_bounds__(256) build_lists_kernel(const void* __restrict__ idx_raw) {
    asm volatile("griddepcontrol.launch_dependents;" ::: "memory");

    __shared__ unsigned s_epoch;
    __shared__ int s_is64;
    int t = threadIdx.x;
    if (t == 0) {
        s_epoch = (atomicAdd(&g_ctr, 1u) >> 3) + 1u;
        s_is64 = 1;
    }
    __syncthreads();
    if (t == 0 && blockIdx.x == 0) g_epoch = s_epoch;

    const unsigned long long* w = (const unsigned long long*)idx_raw;
    #pragma unroll
    for (int i = t; i < 3072; i += 256)
        if ((w[i] >> 32) != 0ull) s_is64 = 0;   // benign race
    __syncthreads();

    int n = blockIdx.x * 256 + t;               // < NN
    int b, hb, wb;
    if (s_is64) {
        const long long* idx = (const long long*)idx_raw;
        b  = (int)idx[3 * n + 0];
        hb = (int)idx[3 * n + 1];
        wb = (int)idx[3 * n + 2];
    } else {
        const int* idx = (const int*)idx_raw;
        b  = idx[3 * n + 0];
        hb = idx[3 * n + 1];
        wb = idx[3 * n + 2];
    }
    int slot = (b << 10) | (hb << 5) | wb;
    unsigned long long packed = ((unsigned long long)s_epoch << 32) | (unsigned)n;
    unsigned long long old = atomicExch(&g_slot[slot & (NSLOTS - 1)], packed);
    g_next[n] = ((unsigned)(old >> 32) == s_epoch) ? (int)(old & 0xffffffffu) : -1;
}

__device__ __forceinline__ void ldg256cs(const float* p, float* v) {
    asm volatile("ld.global.cs.v8.f32 {%0,%1,%2,%3,%4,%5,%6,%7}, [%8];"
                 : "=f"(v[0]), "=f"(v[1]), "=f"(v[2]), "=f"(v[3]),
                   "=f"(v[4]), "=f"(v[5]), "=f"(v[6]), "=f"(v[7])
                 : "l"(p));
}

__device__ __forceinline__ void stg256cs(float* p, const float* v) {
    asm volatile("st.global.cs.v8.f32 [%0], {%1,%2,%3,%4,%5,%6,%7,%8};"
                 :: "l"(p),
                    "f"(v[0]), "f"(v[1]), "f"(v[2]), "f"(v[3]),
                    "f"(v[4]), "f"(v[5]), "f"(v[6]), "f"(v[7])
                 : "memory");
}

__device__ __forceinline__ unsigned slot_of(unsigned i8) {
    unsigned w8 = i8 & 63u;
    unsigned h  = (i8 >> 6) & 511u;
    unsigned b  = i8 >> 21;
    return (b << 10) | ((h >> 4) << 5) | (w8 >> 1);
}

// Persistent: 1216 blocks x 256 threads, grid-stride over 8,388,608 float8.
__global__ void __launch_bounds__(256) scatter_main_kernel(
    const float* __restrict__ in,
    const float* __restrict__ g,
    float* __restrict__ out)
{
    unsigned i8 = blockIdx.x * 256u + threadIdx.x;   // always < TOTAL8

    // prefetch first in-tile before the PDL wait
    float v[8];
    ldg256cs(in + ((size_t)i8 << 3), v);

    asm volatile("griddepcontrol.wait;" ::: "memory");

    const unsigned epoch = g_epoch;
    unsigned long long hv = g_slot[slot_of(i8)];

    for (;;) {
        int p = ((unsigned)(hv >> 32) == epoch) ? (int)(hv & 0xffffffffu) : -1;

        unsigned h  = (i8 >> 6) & 511u;
        unsigned c  = (i8 >> 15) & 63u;
        // patch offset in float8 units: p*2048 + c*32 + (h&15)*2 + (i8&1)
        unsigned local8 = (c << 5) | ((h & 15u) << 1) | (i8 & 1u);

        unsigned i8n = i8 + STRIDE8;
        bool more = (i8n < TOTAL8);

        float vn[8];
        unsigned long long hvn = 0;
        if (more) {                               // prefetch next iteration
            ldg256cs(in + ((size_t)i8n << 3), vn);
            hvn = g_slot[slot_of(i8n)];
        }

        while (p >= 0) {
            float gv[8];
            ldg256cs(g + (((size_t)((unsigned)p << 11) + local8) << 3), gv);
            #pragma unroll
            for (int j = 0; j < 8; j++) v[j] += gv[j];
            p = g_next[p];
        }

        stg256cs(out + ((size_t)i8 << 3), v);

        if (!more) break;
        i8 = i8n;
        hv = hvn;
        #pragma unroll
        for (int j = 0; j < 8; j++) v[j] = vn[j];
    }
}

extern "C" void kernel_launch(void* const* d_in, const int* in_sizes, int n_in,
                              void* d_out, int out_size) {
    const float* input    = (const float*)d_in[0];
    const float* gathered = (const float*)d_in[1];
    const void*  indices  = d_in[2];
    float* out = (float*)d_out;

    build_lists_kernel<<<NN / 256, 256>>>(indices);

    cudaLaunchConfig_t cfg = {};
    cfg.gridDim  = dim3(GRID_MAIN);
    cfg.blockDim = dim3(256);
    cfg.stream   = 0;
    cudaLaunchAttribute at[1];
    at[0].id = cudaLaunchAttributeProgrammaticStreamSerialization;
    at[0].val.programmaticStreamSerializationAllowed = 1;
    cfg.attrs = at;
    cfg.numAttrs = 1;
    cudaLaunchKernelEx(&cfg, scatter_main_kernel, input, gathered, out);
}

// round 10
// speedup vs baseline: 1.2430x; 1.2430x over previous
#include <cuda_runtime.h>
#include <cstdint>

// input f32 [4,64,512,512], gathered f32 [2048,64,16,16], indices (b,hb,wb)
// int32 or int64 (detected on device). stride==kernel==16 -> 4096 disjoint
// 16x16 slots; duplicates via per-slot linked lists. Main pass:
// out = in + sum(patches in slot), 640MB traffic, 256-bit streaming accesses,
// one-shot 32768x256 grid (R9 showed persistent+prefetch loses 25us to
// occupancy/serialization; high warp count does the latency hiding here).
//
// Epoch trick removes head-init: heads are u64 (epoch<<32|patch). g_ctr is
// bumped once per build block (8/launch); all blocks of one launch share
// epoch=(ctr>>3)+1 since launches are stream-serialized. Stale heads fail the
// epoch compare. Main kernel is PDL-launched; its in-load precedes
// griddepcontrol.wait so the launch ramp overlaps the build kernel.

#define BB 4
#define CC 64
#define HH 512
#define WW 512
#define NN 2048
#define NSLOTS 4096   // BB * 32 * 32

__device__ unsigned long long g_slot[NSLOTS];  // (epoch<<32) | patch_id
__device__ int g_next[NN];
__device__ unsigned g_ctr;                     // monotonic, +8 per launch

// 8 blocks x 256 threads = exactly NN.
// Dtype detect per block: first 3072 u64 words = 24576B (full buffer if
// int32 = N*3*4, half if int64). Genuine int64 index values are < 512 so all
// high words are zero; int32 data read as u64 carries the neighboring field
// in the high word (nonzero somewhere with overwhelming probability).
__global__ void __launch_bounds__(256) build_lists_kernel(const void* __restrict__ idx_raw) {
    __shared__ unsigned s_epoch;
    __shared__ int s_is64;
    int t = threadIdx.x;
    if (t == 0) {
        s_epoch = (atomicAdd(&g_ctr, 1u) >> 3) + 1u;
        s_is64 = 1;
    }
    __syncthreads();

    const unsigned long long* w = (const unsigned long long*)idx_raw;
    #pragma unroll
    for (int i = t; i < 3072; i += 256)
        if ((w[i] >> 32) != 0ull) s_is64 = 0;   // benign race
    __syncthreads();

    int n = blockIdx.x * 256 + t;               // < NN
    int b, hb, wb;
    if (s_is64) {
        const long long* idx = (const long long*)idx_raw;
        b  = (int)idx[3 * n + 0];
        hb = (int)idx[3 * n + 1];
        wb = (int)idx[3 * n + 2];
    } else {
        const int* idx = (const int*)idx_raw;
        b  = idx[3 * n + 0];
        hb = idx[3 * n + 1];
        wb = idx[3 * n + 2];
    }
    int slot = (b << 10) | (hb << 5) | wb;
    unsigned long long packed = ((unsigned long long)s_epoch << 32) | (unsigned)n;
    unsigned long long old = atomicExch(&g_slot[slot & (NSLOTS - 1)], packed);
    g_next[n] = ((unsigned)(old >> 32) == s_epoch) ? (int)(old & 0xffffffffu) : -1;

    asm volatile("griddepcontrol.launch_dependents;" ::: "memory");
}

__device__ __forceinline__ void ldg256cs(const float* p, float* v) {
    asm volatile("ld.global.cs.v8.f32 {%0,%1,%2,%3,%4,%5,%6,%7}, [%8];"
                 : "=f"(v[0]), "=f"(v[1]), "=f"(v[2]), "=f"(v[3]),
                   "=f"(v[4]), "=f"(v[5]), "=f"(v[6]), "=f"(v[7])
                 : "l"(p));
}

__device__ __forceinline__ void stg256cs(float* p, const float* v) {
    asm volatile("st.global.cs.v8.f32 [%0], {%1,%2,%3,%4,%5,%6,%7,%8};"
                 :: "l"(p),
                    "f"(v[0]), "f"(v[1]), "f"(v[2]), "f"(v[3]),
                    "f"(v[4]), "f"(v[5]), "f"(v[6]), "f"(v[7])
                 : "memory");
}

// One float8 (32B) per thread. 8,388,608 float8 -> 32768 blocks of 256.
__global__ void __launch_bounds__(256) scatter_main_kernel(
    const float* __restrict__ in,
    const float* __restrict__ g,
    float* __restrict__ out)
{
    unsigned i8 = blockIdx.x * 256u + threadIdx.x;   // < 2^23

    unsigned w8 = i8 & 63u;           // float8 column: w = w8*8
    unsigned h  = (i8 >> 6) & 511u;
    unsigned c  = (i8 >> 15) & 63u;
    unsigned b  = i8 >> 21;

    unsigned slot = (b << 10) | ((h >> 4) << 5) | (w8 >> 1);

    float v[8];
    ldg256cs(in + ((size_t)i8 << 3), v);

    // wait for build grid COMPLETION (PDL edge) before touching lists
    asm volatile("griddepcontrol.wait;" ::: "memory");

    unsigned epoch = ((g_ctr - 1u) >> 3) + 1u;
    unsigned long long hv = g_slot[slot];
    int p = ((unsigned)(hv >> 32) == epoch) ? (int)(hv & 0xffffffffu) : -1;

    if (p >= 0) {
        // patch offset in float8 units: p*2048 + c*32 + (h&15)*2 + (w8&1)
        unsigned local8 = (c << 5) | ((h & 15u) << 1) | (w8 & 1u);
        do {
            float gv[8];
            ldg256cs(g + (((size_t)((unsigned)p << 11) + local8) << 3), gv);
            #pragma unroll
            for (int j = 0; j < 8; j++) v[j] += gv[j];
            p = g_next[p];
        } while (p >= 0);
    }

    stg256cs(out + ((size_t)i8 << 3), v);
}

extern "C" void kernel_launch(void* const* d_in, const int* in_sizes, int n_in,
                              void* d_out, int out_size) {
    const float* input    = (const float*)d_in[0];
    const float* gathered = (const float*)d_in[1];
    const void*  indices  = d_in[2];
    float* out = (float*)d_out;

    build_lists_kernel<<<NN / 256, 256>>>(indices);

    const unsigned total8 = (unsigned)(BB * CC * HH * WW) / 8u;  // 8,388,608
    cudaLaunchConfig_t cfg = {};
    cfg.gridDim  = dim3(total8 / 256);
    cfg.blockDim = dim3(256);
    cfg.stream   = 0;
    cudaLaunchAttribute at[1];
    at[0].id = cudaLaunchAttributeProgrammaticStreamSerialization;
    at[0].val.programmaticStreamSerializationAllowed = 1;
    cfg.attrs = at;
    cfg.numAttrs = 1;
    cudaLaunchKernelEx(&cfg, scatter_main_kernel, input, gathered, out);
}

// round 11
// speedup vs baseline: 1.2835x; 1.0326x over previous
#include <cuda_runtime.h>
#include <cstdint>

// input f32 [4,64,512,512], gathered f32 [2048,64,16,16], indices (b,hb,wb)
// int32 or int64 (detected on device). stride==kernel==16 -> 4096 disjoint
// 16x16 slots; duplicates via per-slot linked lists. Main pass:
// out = in + sum(patches in slot), 640MB traffic, 256-bit streaming accesses,
// one-shot 32768x256 grid.
//
// Findings locked in: persistent+prefetch loses 25us (occupancy), PDL loses
// ~1-2us total (main CTAs ramp early and absorb the build tail in their
// duration). Epoch trick removes the head-init kernel: heads are u64
// (epoch<<32|patch); g_ctr bumps once per build block (8/launch) so all
// blocks of one launch share epoch=(ctr>>3)+1 (launches stream-serialized);
// stale heads from prior launches/replays fail the epoch compare.

#define BB 4
#define CC 64
#define HH 512
#define WW 512
#define NN 2048
#define NSLOTS 4096   // BB * 32 * 32

__device__ unsigned long long g_slot[NSLOTS];  // (epoch<<32) | patch_id
__device__ int g_next[NN];
__device__ unsigned g_ctr;                     // monotonic, +8 per launch

// 8 blocks x 256 threads = exactly NN.
// Dtype detect per block: first 3072 u64 words = 24576B (full buffer if
// int32 = N*3*4, half if int64). Genuine int64 index values are < 512 so all
// high words are zero; int32 data read as u64 carries the neighboring field
// in the high word (nonzero somewhere with overwhelming probability).
__global__ void __launch_bounds__(256) build_lists_kernel(const void* __restrict__ idx_raw) {
    __shared__ unsigned s_epoch;
    __shared__ int s_is64;
    int t = threadIdx.x;
    if (t == 0) {
        s_epoch = (atomicAdd(&g_ctr, 1u) >> 3) + 1u;
        s_is64 = 1;
    }
    __syncthreads();

    const unsigned long long* w = (const unsigned long long*)idx_raw;
    #pragma unroll
    for (int i = t; i < 3072; i += 256)
        if ((w[i] >> 32) != 0ull) s_is64 = 0;   // benign race
    __syncthreads();

    int n = blockIdx.x * 256 + t;               // < NN
    int b, hb, wb;
    if (s_is64) {
        const long long* idx = (const long long*)idx_raw;
        b  = (int)idx[3 * n + 0];
        hb = (int)idx[3 * n + 1];
        wb = (int)idx[3 * n + 2];
    } else {
        const int* idx = (const int*)idx_raw;
        b  = idx[3 * n + 0];
        hb = idx[3 * n + 1];
        wb = idx[3 * n + 2];
    }
    int slot = (b << 10) | (hb << 5) | wb;
    unsigned long long packed = ((unsigned long long)s_epoch << 32) | (unsigned)n;
    unsigned long long old = atomicExch(&g_slot[slot & (NSLOTS - 1)], packed);
    g_next[n] = ((unsigned)(old >> 32) == s_epoch) ? (int)(old & 0xffffffffu) : -1;
}

__device__ __forceinline__ void ldg256cs(const float* p, float* v) {
    asm volatile("ld.global.cs.v8.f32 {%0,%1,%2,%3,%4,%5,%6,%7}, [%8];"
                 : "=f"(v[0]), "=f"(v[1]), "=f"(v[2]), "=f"(v[3]),
                   "=f"(v[4]), "=f"(v[5]), "=f"(v[6]), "=f"(v[7])
                 : "l"(p));
}

__device__ __forceinline__ void stg256cs(float* p, const float* v) {
    asm volatile("st.global.cs.v8.f32 [%0], {%1,%2,%3,%4,%5,%6,%7,%8};"
                 :: "l"(p),
                    "f"(v[0]), "f"(v[1]), "f"(v[2]), "f"(v[3]),
                    "f"(v[4]), "f"(v[5]), "f"(v[6]), "f"(v[7])
                 : "memory");
}

// One float8 (32B) per thread. 8,388,608 float8 -> 32768 blocks of 256.
__global__ void __launch_bounds__(256) scatter_main_kernel(
    const float* __restrict__ in,
    const float* __restrict__ g,
    float* __restrict__ out)
{
    unsigned i8 = blockIdx.x * 256u + threadIdx.x;   // < 2^23

    unsigned w8 = i8 & 63u;           // float8 column: w = w8*8
    unsigned h  = (i8 >> 6) & 511u;
    unsigned c  = (i8 >> 15) & 63u;
    unsigned b  = i8 >> 21;

    unsigned slot = (b << 10) | ((h >> 4) << 5) | (w8 >> 1);

    float v[8];
    ldg256cs(in + ((size_t)i8 << 3), v);

    unsigned epoch = ((g_ctr - 1u) >> 3) + 1u;
    unsigned long long hv = g_slot[slot];
    int p = ((unsigned)(hv >> 32) == epoch) ? (int)(hv & 0xffffffffu) : -1;

    if (p >= 0) {
        // patch offset in float8 units: p*2048 + c*32 + (h&15)*2 + (w8&1)
        unsigned local8 = (c << 5) | ((h & 15u) << 1) | (w8 & 1u);
        do {
            float gv[8];
            ldg256cs(g + (((size_t)((unsigned)p << 11) + local8) << 3), gv);
            #pragma unroll
            for (int j = 0; j < 8; j++) v[j] += gv[j];
            p = g_next[p];
        } while (p >= 0);
    }

    stg256cs(out + ((size_t)i8 << 3), v);
}

extern "C" void kernel_launch(void* const* d_in, const int* in_sizes, int n_in,
                              void* d_out, int out_size) {
    const float* input    = (const float*)d_in[0];
    const float* gathered = (const float*)d_in[1];
    const void*  indices  = d_in[2];
    float* out = (float*)d_out;

    build_lists_kernel<<<NN / 256, 256>>>(indices);

    const unsigned total8 = (unsigned)(BB * CC * HH * WW) / 8u;  // 8,388,608
    scatter_main_kernel<<<total8 / 256, 256>>>(input, gathered, out);
}

// round 12
// speedup vs baseline: 1.2843x; 1.0006x over previous
#include <cuda_runtime.h>
#include <cstdint>

// input f32 [4,64,512,512], gathered f32 [2048,64,16,16], indices (b,hb,wb)
// int32 or int64 (detected on device, cheaply). stride==kernel==16 -> 4096
// disjoint 16x16 slots; duplicates via per-slot linked lists. Main pass:
// out = in + sum(patches in slot), 640MB traffic, 256-bit streaming accesses,
// one-shot 32768x256 grid.
//
// Locked-in findings: persistent+prefetch loses 25us (occupancy/serialization);
// PDL loses ~1-2us (main CTAs ramp early and absorb the build tail);
// epoch-heads remove the init kernel. Heads are u64 (epoch<<32|patch); g_ctr
// bumps once per build block (8/launch) so all blocks of one launch share
// epoch=(ctr>>3)+1 (launches are stream-serialized); stale heads from prior
// launches/graph replays fail the epoch compare.

#define BB 4
#define CC 64
#define HH 512
#define WW 512
#define NN 2048
#define NSLOTS 4096   // BB * 32 * 32

__device__ unsigned long long g_slot[NSLOTS];  // (epoch<<32) | patch_id
__device__ int g_next[NN];
__device__ unsigned g_ctr;                     // monotonic, +8 per launch

// 8 blocks x 256 threads = exactly NN.
// Cheap dtype detect per block: each thread checks ONE u64 of the first
// 256 words (2048B, always within the buffer: int32 size = 24576B).
// Genuine int64 index values are < 512 -> high words all zero. int32 data
// read as u64 carries a neighboring field (b in [0,4), hb/wb in [0,32)) in
// the high word; all 256 being zero has probability ~(1/32)^170 ~ 0.
__global__ void __launch_bounds__(256) build_lists_kernel(const void* __restrict__ idx_raw) {
    __shared__ unsigned s_epoch;
    __shared__ int s_is64;
    int t = threadIdx.x;
    if (t == 0) {
        s_epoch = (atomicAdd(&g_ctr, 1u) >> 3) + 1u;
        s_is64 = 1;
    }
    __syncthreads();

    const unsigned long long* w = (const unsigned long long*)idx_raw;
    if ((w[t] >> 32) != 0ull) s_is64 = 0;       // benign race
    __syncthreads();

    int n = blockIdx.x * 256 + t;               // < NN
    int b, hb, wb;
    if (s_is64) {
        const long long* idx = (const long long*)idx_raw;
        b  = (int)idx[3 * n + 0];
        hb = (int)idx[3 * n + 1];
        wb = (int)idx[3 * n + 2];
    } else {
        const int* idx = (const int*)idx_raw;
        b  = idx[3 * n + 0];
        hb = idx[3 * n + 1];
        wb = idx[3 * n + 2];
    }
    int slot = (b << 10) | (hb << 5) | wb;
    unsigned long long packed = ((unsigned long long)s_epoch << 32) | (unsigned)n;
    unsigned long long old = atomicExch(&g_slot[slot & (NSLOTS - 1)], packed);
    g_next[n] = ((unsigned)(old >> 32) == s_epoch) ? (int)(old & 0xffffffffu) : -1;
}

__device__ __forceinline__ void ldg256cs(const float* p, float* v) {
    asm volatile("ld.global.cs.v8.f32 {%0,%1,%2,%3,%4,%5,%6,%7}, [%8];"
                 : "=f"(v[0]), "=f"(v[1]), "=f"(v[2]), "=f"(v[3]),
                   "=f"(v[4]), "=f"(v[5]), "=f"(v[6]), "=f"(v[7])
                 : "l"(p));
}

__device__ __forceinline__ void stg256cs(float* p, const float* v) {
    asm volatile("st.global.cs.v8.f32 [%0], {%1,%2,%3,%4,%5,%6,%7,%8};"
                 :: "l"(p),
                    "f"(v[0]), "f"(v[1]), "f"(v[2]), "f"(v[3]),
                    "f"(v[4]), "f"(v[5]), "f"(v[6]), "f"(v[7])
                 : "memory");
}

// One float8 (32B) per thread. 8,388,608 float8 -> 32768 blocks of 256.
__global__ void __launch_bounds__(256) scatter_main_kernel(
    const float* __restrict__ in,
    const float* __restrict__ g,
    float* __restrict__ out)
{
    unsigned i8 = blockIdx.x * 256u + threadIdx.x;   // < 2^23

    unsigned w8 = i8 & 63u;           // float8 column: w = w8*8
    unsigned h  = (i8 >> 6) & 511u;
    unsigned c  = (i8 >> 15) & 63u;
    unsigned b  = i8 >> 21;

    unsigned slot = (b << 10) | ((h >> 4) << 5) | (w8 >> 1);

    float v[8];
    ldg256cs(in + ((size_t)i8 << 3), v);

    unsigned epoch = ((g_ctr - 1u) >> 3) + 1u;
    unsigned long long hv = g_slot[slot];
    int p = ((unsigned)(hv >> 32) == epoch) ? (int)(hv & 0xffffffffu) : -1;

    if (p >= 0) {
        // patch offset in float8 units: p*2048 + c*32 + (h&15)*2 + (w8&1)
        unsigned local8 = (c << 5) | ((h & 15u) << 1) | (w8 & 1u);
        do {
            float gv[8];
            ldg256cs(g + (((size_t)((unsigned)p << 11) + local8) << 3), gv);
            #pragma unroll
            for (int j = 0; j < 8; j++) v[j] += gv[j];
            p = g_next[p];
        } while (p >= 0);
    }

    stg256cs(out + ((size_t)i8 << 3), v);
}

extern "C" void kernel_launch(void* const* d_in, const int* in_sizes, int n_in,
                              void* d_out, int out_size) {
    const float* input    = (const float*)d_in[0];
    const float* gathered = (const float*)d_in[1];
    const void*  indices  = d_in[2];
    float* out = (float*)d_out;

    build_lists_kernel<<<NN / 256, 256>>>(indices);

    const unsigned total8 = (unsigned)(BB * CC * HH * WW) / 8u;  // 8,388,608
    scatter_main_kernel<<<total8 / 256, 256>>>(input, gathered, out);
}